// round 14
// baseline (speedup 1.0000x reference)
#include <cuda_runtime.h>
#include <cuda_bf16.h>
#include <cstdint>

#define ND 4096
#define NTE (ND * (size_t)ND)

// ---------------- scratch (device globals; no allocation allowed) ----------
__device__ __align__(1024) __nv_bfloat16 g_Ah[NTE];   // tril(A) hi, [M,K] K-major
__device__ __align__(1024) __nv_bfloat16 g_Al[NTE];   // tril(A) lo
__device__ __align__(1024) __nv_bfloat16 g_Bth[NTE];  // tril(B)^T hi, [N,K] K-major
__device__ __align__(1024) __nv_bfloat16 g_Btl[NTE];  // tril(B)^T lo

// ---------------- helpers ---------------------------------------------------
static __device__ __forceinline__ uint32_t smem_u32(const void* p) {
    return (uint32_t)__cvta_generic_to_shared(p);
}
static __device__ __forceinline__ void cp_async16(uint32_t dst, const void* src) {
    asm volatile("cp.async.cg.shared.global [%0], [%1], 16;" :: "r"(dst), "l"(src));
}
static __device__ __forceinline__ void cp_commit() {
    asm volatile("cp.async.commit_group;" ::: "memory");
}
static __device__ __forceinline__ void cp_wait2() {
    asm volatile("cp.async.wait_group 2;" ::: "memory");
}
static __device__ __forceinline__ void ldsm4(uint32_t& r0, uint32_t& r1,
                                             uint32_t& r2, uint32_t& r3, uint32_t a) {
    asm volatile("ldmatrix.sync.aligned.m8n8.x4.shared.b16 {%0,%1,%2,%3}, [%4];"
                 : "=r"(r0), "=r"(r1), "=r"(r2), "=r"(r3) : "r"(a));
}
static __device__ __forceinline__ void mma16816(float* d, const uint32_t* a,
                                                const uint32_t* b) {
    asm volatile(
        "mma.sync.aligned.m16n8k16.row.col.f32.bf16.bf16.f32 "
        "{%0,%1,%2,%3}, {%4,%5,%6,%7}, {%8,%9}, {%0,%1,%2,%3};"
        : "+f"(d[0]), "+f"(d[1]), "+f"(d[2]), "+f"(d[3])
        : "r"(a[0]), "r"(a[1]), "r"(a[2]), "r"(a[3]), "r"(b[0]), "r"(b[1]));
}
static __device__ __forceinline__ void redadd(float* p, float v) {
    asm volatile("red.global.add.f32 [%0], %1;" :: "l"(p), "f"(v) : "memory");
}

// swizzled smem byte offset: row r, 16B chunk c (0..3); 64B rows
static __device__ __forceinline__ uint32_t swz(int r, int c) {
    return (uint32_t)(r * 64 + ((c ^ ((r >> 1) & 3)) << 4));
}

// ------ pre-pass: zero C + mask + bf16 hi/lo split of A (lower blocks) ------
__global__ void convert_split_A(const float* __restrict__ A, float* __restrict__ C) {
    size_t idx  = (size_t)blockIdx.x * blockDim.x + threadIdx.x;   // one float4
    size_t base = idx * 4;
    int i = (int)(base >> 12);     // row
    int k = (int)(base & 4095);    // col
    // zero C everywhere (atomic targets + upper triangle)
    *(float4*)(C + base) = make_float4(0.f, 0.f, 0.f, 0.f);
    if ((k >> 7) > (i >> 7)) return;   // strictly-upper 128-blocks never read
    float4 v = *(const float4*)(A + base);
    float vv[4] = {v.x, v.y, v.z, v.w};
    __nv_bfloat16 h[4], l[4];
#pragma unroll
    for (int e = 0; e < 4; ++e) {
        float x = ((k + e) <= i) ? vv[e] : 0.0f;
        __nv_bfloat16 hi = __float2bfloat16(x);
        float res = x - __bfloat162float(hi);
        h[e] = hi;
        l[e] = __float2bfloat16(res);
    }
    __nv_bfloat162* ah = (__nv_bfloat162*)(g_Ah + base);
    __nv_bfloat162* al = (__nv_bfloat162*)(g_Al + base);
    ah[0] = __nv_bfloat162(h[0], h[1]); ah[1] = __nv_bfloat162(h[2], h[3]);
    al[0] = __nv_bfloat162(l[0], l[1]); al[1] = __nv_bfloat162(l[2], l[3]);
}

// ---------------- pre-pass: mask + transpose + split of B (64x64 tiles) -----
__global__ void transpose_split_B(const float* __restrict__ B) {
    __shared__ float tile[64][65];
    const int bk = blockIdx.y;
    const int bn = blockIdx.x;
    if ((bn >> 1) > (bk >> 1)) return;   // keep only k128-block >= n128-block
    const int tx = threadIdx.x;  // 0..63
    const int ty = threadIdx.y;  // 0..3
    const int k0 = bk * 64, n0 = bn * 64;
#pragma unroll
    for (int r = ty; r < 64; r += 4) {
        int k = k0 + r, n = n0 + tx;
        float v = B[(size_t)k * ND + n];
        tile[r][tx] = (n <= k) ? v : 0.0f;
    }
    __syncthreads();
#pragma unroll
    for (int r = ty; r < 64; r += 4) {
        int n = n0 + r, k = k0 + tx;
        float x = tile[tx][r];   // = masked B[k][n]
        __nv_bfloat16 hi = __float2bfloat16(x);
        float res = x - __bfloat162float(hi);
        g_Bth[(size_t)n * ND + k] = hi;
        g_Btl[(size_t)n * ND + k] = __float2bfloat16(res);
    }
}

// -------- main GEMM: CTA 256x128, warp tile 64x64, split-K (K=512) ----------
#define STAGES 4
#define O_AH 0
#define O_AL 16384
#define O_BH 32768
#define O_BL 40960
#define STAGE_BYTES 49152                   // Ah,Al 16KB + Bh,Bl 8KB
#define GEMM_SMEM (STAGES * STAGE_BYTES)    // 196608
#define CH 16                               // K-stages per chunk (K=512)
// units = sum_e (16 - e/2) * ceil((e+1)/4) = 888
#define UNITS 888

__global__ __launch_bounds__(256, 1)
void trimm_gemm(float* __restrict__ C) {
    extern __shared__ char smem[];
    const uint32_t sb = smem_u32(smem);
    const int tid = threadIdx.x;
    const int wid = tid >> 5;      // 0..7
    const int lid = tid & 31;
    const int wm = wid & 3;        // 0..3 (M, 64 rows each)
    const int wn = wid >> 2;       // 0..1 (N, 64 cols each)

    // ---- work-unit decode: deepest diagonals first ------------------------
    int id = blockIdx.x;
    int e, cum = 0, nch = 1;
    for (e = 31; e >= 0; --e) {
        nch = (e + 4) >> 2;                  // ceil((e+1)/4)
        int cnt = (16 - (e >> 1)) * nch;
        if (id < cum + cnt) break;
        cum += cnt;
    }
    const int rem = id - cum;
    const int ti  = rem / nch;
    const int cch = rem % nch;
    const int BI  = (e >> 1) + ti;           // 256-row band 0..15
    const int bj  = 2 * BI + 1 - e;          // 128-col block

    const int KTtile = (e + 1) * 4;          // K=32 stages in the tile
    const int ks0    = cch * CH;
    const int KTc    = min(CH, KTtile - ks0);   // 4..16
    const int kt0    = bj * 128 + ks0 * 32;

    const int arow = BI * 256, brow = bj * 128;

    // cp.async coords: A tiles 1024 chunks (4/thread), B tiles 512 (2/thread)
    const int cg = tid & 3;

    auto issue = [&](int s, int kt) {
        uint32_t st = sb + (uint32_t)s * STAGE_BYTES;
#pragma unroll
        for (int q = 0; q < 4; ++q) {
            int rg = (tid + q * 256) >> 2;
            cp_async16(st + O_AH + swz(rg, cg), g_Ah + (size_t)(arow + rg) * ND + kt + cg * 8);
            cp_async16(st + O_AL + swz(rg, cg), g_Al + (size_t)(arow + rg) * ND + kt + cg * 8);
        }
#pragma unroll
        for (int q = 0; q < 2; ++q) {
            int rg = (tid + q * 256) >> 2;
            cp_async16(st + O_BH + swz(rg, cg), g_Bth + (size_t)(brow + rg) * ND + kt + cg * 8);
            cp_async16(st + O_BL + swz(rg, cg), g_Btl + (size_t)(brow + rg) * ND + kt + cg * 8);
        }
    };

    float acc[4][8][4];
#pragma unroll
    for (int a = 0; a < 4; ++a)
#pragma unroll
        for (int b = 0; b < 8; ++b)
#pragma unroll
            for (int c = 0; c < 4; ++c) acc[a][b][c] = 0.f;

    const int g  = lid >> 3;   // 0..3
    const int rr = lid & 7;

    auto compute_stage = [&](int slot) {
        const uint32_t st = sb + (uint32_t)slot * STAGE_BYTES;
#pragma unroll
        for (int ks = 0; ks < 2; ++ks) {
            const int c0 = ks * 2;
            uint32_t ah[4][4], al[4][4], bh[8][2], bl[8][2];
#pragma unroll
            for (int tm = 0; tm < 4; ++tm) {
                int r = wm * 64 + tm * 16 + (g & 1) * 8 + rr;
                uint32_t off = swz(r, c0 + (g >> 1));
                ldsm4(ah[tm][0], ah[tm][1], ah[tm][2], ah[tm][3], st + O_AH + off);
                ldsm4(al[tm][0], al[tm][1], al[tm][2], al[tm][3], st + O_AL + off);
            }
#pragma unroll
            for (int p = 0; p < 4; ++p) {
                int r = wn * 64 + p * 16 + (g >> 1) * 8 + rr;
                uint32_t off = swz(r, c0 + (g & 1));
                uint32_t h0, h1, h2, h3;
                ldsm4(h0, h1, h2, h3, st + O_BH + off);
                bh[p * 2 + 0][0] = h0; bh[p * 2 + 0][1] = h1;
                bh[p * 2 + 1][0] = h2; bh[p * 2 + 1][1] = h3;
                ldsm4(h0, h1, h2, h3, st + O_BL + off);
                bl[p * 2 + 0][0] = h0; bl[p * 2 + 0][1] = h1;
                bl[p * 2 + 1][0] = h2; bl[p * 2 + 1][1] = h3;
            }
#pragma unroll
            for (int tm = 0; tm < 4; ++tm)
#pragma unroll
                for (int tn = 0; tn < 8; ++tn) {
                    mma16816(acc[tm][tn], ah[tm], bh[tn]);
                    mma16816(acc[tm][tn], ah[tm], bl[tn]);
                    mma16816(acc[tm][tn], al[tm], bh[tn]);
                }
        }
    };

    // prologue: stages 0,1 (KTc >= 4)
    issue(0, kt0);      cp_commit();
    issue(1, kt0 + 32); cp_commit();

    // one stage per barrier; commits = j+3 -> wait2 completes stages <= j.
    // slot check (STAGES=4, skew<1 barrier): write (j+2)&3 vs laggard read
    // (j-1)&3 -> diff 3 != 0 mod 4 -> safe.
    for (int j = 0; j < KTc; ++j) {
        if (j + 2 < KTc) issue((j + 2) & 3, kt0 + (j + 2) * 32);
        cp_commit();
        cp_wait2();
        __syncthreads();
        compute_stage(j & 3);
    }

    // epilogue
    if (nch == 1) {
#pragma unroll
        for (int tm = 0; tm < 4; ++tm)
#pragma unroll
            for (int tn = 0; tn < 8; ++tn) {
                int row = arow + wm * 64 + tm * 16 + (lid >> 2);
                int col = brow + wn * 64 + tn * 8 + (lid & 3) * 2;
                *(float2*)(C + (size_t)row * ND + col) =
                    make_float2(acc[tm][tn][0], acc[tm][tn][1]);
                *(float2*)(C + (size_t)(row + 8) * ND + col) =
                    make_float2(acc[tm][tn][2], acc[tm][tn][3]);
            }
    } else {
#pragma unroll
        for (int tm = 0; tm < 4; ++tm)
#pragma unroll
            for (int tn = 0; tn < 8; ++tn) {
                int row = arow + wm * 64 + tm * 16 + (lid >> 2);
                int col = brow + wn * 64 + tn * 8 + (lid & 3) * 2;
                float* p0 = C + (size_t)row * ND + col;
                float* p1 = C + (size_t)(row + 8) * ND + col;
                redadd(p0,     acc[tm][tn][0]);
                redadd(p0 + 1, acc[tm][tn][1]);
                redadd(p1,     acc[tm][tn][2]);
                redadd(p1 + 1, acc[tm][tn][3]);
            }
    }
}

// ---------------- launch ----------------------------------------------------
extern "C" void kernel_launch(void* const* d_in, const int* in_sizes, int n_in,
                              void* d_out, int out_size) {
    const float* A = (const float*)d_in[0];
    const float* B = (const float*)d_in[1];
    float* C = (float*)d_out;

    cudaFuncSetAttribute(trimm_gemm, cudaFuncAttributeMaxDynamicSharedMemorySize, GEMM_SMEM);

    convert_split_A<<<16384, 256>>>(A, C);
    transpose_split_B<<<dim3(64, 64), dim3(64, 4)>>>(B);
    trimm_gemm<<<UNITS, 256, GEMM_SMEM>>>(C);
}

// round 15
// speedup vs baseline: 1.9373x; 1.9373x over previous
#include <cuda_runtime.h>
#include <cuda_fp16.h>
#include <cstdint>

#define ND 4096
#define NTE (ND * (size_t)ND)

// ---------------- scratch (device globals; no allocation allowed) ----------
__device__ __align__(1024) __half g_A16[NTE];   // fp16(tril(A)), [M,K] K-major
__device__ __align__(1024) __half g_B16[NTE];   // fp16(tril(B)^T), [N,K] K-major

// ---------------- helpers ---------------------------------------------------
static __device__ __forceinline__ uint32_t smem_u32(const void* p) {
    return (uint32_t)__cvta_generic_to_shared(p);
}
static __device__ __forceinline__ void cp_async16(uint32_t dst, const void* src) {
    asm volatile("cp.async.cg.shared.global [%0], [%1], 16;" :: "r"(dst), "l"(src));
}
static __device__ __forceinline__ void cp_commit() {
    asm volatile("cp.async.commit_group;" ::: "memory");
}
static __device__ __forceinline__ void cp_wait2() {
    asm volatile("cp.async.wait_group 2;" ::: "memory");
}
static __device__ __forceinline__ void ldsm4(uint32_t& r0, uint32_t& r1,
                                             uint32_t& r2, uint32_t& r3, uint32_t a) {
    asm volatile("ldmatrix.sync.aligned.m8n8.x4.shared.b16 {%0,%1,%2,%3}, [%4];"
                 : "=r"(r0), "=r"(r1), "=r"(r2), "=r"(r3) : "r"(a));
}
static __device__ __forceinline__ void mma16816f(float* d, const uint32_t* a,
                                                 const uint32_t* b) {
    asm volatile(
        "mma.sync.aligned.m16n8k16.row.col.f32.f16.f16.f32 "
        "{%0,%1,%2,%3}, {%4,%5,%6,%7}, {%8,%9}, {%0,%1,%2,%3};"
        : "+f"(d[0]), "+f"(d[1]), "+f"(d[2]), "+f"(d[3])
        : "r"(a[0]), "r"(a[1]), "r"(a[2]), "r"(a[3]), "r"(b[0]), "r"(b[1]));
}
static __device__ __forceinline__ void redadd(float* p, float v) {
    asm volatile("red.global.add.f32 [%0], %1;" :: "l"(p), "f"(v) : "memory");
}

// swizzled smem byte offset inside one 8KB tile: row r (0..127), 16B chunk c (0..3)
static __device__ __forceinline__ uint32_t swz(int r, int c) {
    return (uint32_t)(r * 64 + ((c ^ ((r >> 1) & 3)) << 4));
}

// ------ pre-pass: zero C + mask + fp16 convert of A (lower blocks only) -----
__global__ void convert_A(const float* __restrict__ A, float* __restrict__ C) {
    size_t idx  = (size_t)blockIdx.x * blockDim.x + threadIdx.x;   // one float4
    size_t base = idx * 4;
    int i = (int)(base >> 12);     // row
    int k = (int)(base & 4095);    // col
    *(float4*)(C + base) = make_float4(0.f, 0.f, 0.f, 0.f);
    if ((k >> 7) > (i >> 7)) return;   // strictly-upper 128-blocks never read
    float4 v = *(const float4*)(A + base);
    float vv[4] = {v.x, v.y, v.z, v.w};
    __half h[4];
#pragma unroll
    for (int e = 0; e < 4; ++e) {
        float x = ((k + e) <= i) ? vv[e] : 0.0f;
        h[e] = __float2half_rn(x);
    }
    *(uint2*)(g_A16 + base) = *(uint2*)h;
}

// ---------------- pre-pass: mask + transpose + fp16 of B (64x64 tiles) ------
__global__ void transpose_B(const float* __restrict__ B) {
    __shared__ float tile[64][65];
    const int bk = blockIdx.y;
    const int bn = blockIdx.x;
    if ((bn >> 1) > (bk >> 1)) return;   // keep only k128-block >= n128-block
    const int tx = threadIdx.x;  // 0..63
    const int ty = threadIdx.y;  // 0..3
    const int k0 = bk * 64, n0 = bn * 64;
#pragma unroll
    for (int r = ty; r < 64; r += 4) {
        int k = k0 + r, n = n0 + tx;
        float v = B[(size_t)k * ND + n];
        tile[r][tx] = (n <= k) ? v : 0.0f;
    }
    __syncthreads();
#pragma unroll
    for (int r = ty; r < 64; r += 4) {
        int n = n0 + r, k = k0 + tx;
        g_B16[(size_t)n * ND + k] = __float2half_rn(tile[tx][r]);
    }
}

// -------- main GEMM: fp16 single product, warp tile 64x32, split-K ----------
#define STAGES 6
#define TILE_BYTES 8192                     // one 128x32 fp16 tile
#define O_A 0
#define O_B 8192
#define STAGE_BYTES 16384                   // A + B
#define GEMM_SMEM (STAGES * STAGE_BYTES)    // 98304
#define CH 32                               // K-stages per chunk (K=1024)
#define UNITS 1000

__global__ __launch_bounds__(256, 1)
void trimm_gemm(float* __restrict__ C) {
    extern __shared__ char smem[];
    const uint32_t sb = smem_u32(smem);
    const int tid = threadIdx.x;
    const int wid = tid >> 5;
    const int lid = tid & 31;
    const int wm = wid & 1;        // 0..1 (M)
    const int wn = wid >> 1;       // 0..3 (N)

    // ---- work-unit map: heaviest diagonals first, chunks within tile -------
    int id = blockIdx.x;
    int d, cum = 0, nch = 1;
    for (d = 31; d >= 0; --d) {
        nch = ((d + 1) * 4 + CH - 1) / CH;
        int cnt = (32 - d) * nch;
        if (id < cum + cnt) break;
        cum += cnt;
    }
    const int rem = id - cum;
    const int bj  = rem / nch;
    const int cch = rem % nch;
    const int bi  = bj + d;

    const int KTtile = (d + 1) * 4;
    const int ks0    = cch * CH;
    const int KTc    = min(CH, KTtile - ks0);  // multiple of 4, >= 4
    const int kt0    = bj * 128 + ks0 * 32;

    const int arow = bi * 128, brow = bj * 128;

    // per-thread cp.async chunk coords: two chunks per 8KB tile
    const int r0g = tid >> 2, c0g = tid & 3;
    const int r1g = (tid + 256) >> 2, c1g = tid & 3;

    auto issue = [&](int s, int kt) {
        uint32_t st = sb + (uint32_t)s * STAGE_BYTES;
        cp_async16(st + O_A + swz(r0g, c0g), g_A16 + (size_t)(arow + r0g) * ND + kt + c0g * 8);
        cp_async16(st + O_A + swz(r1g, c1g), g_A16 + (size_t)(arow + r1g) * ND + kt + c1g * 8);
        cp_async16(st + O_B + swz(r0g, c0g), g_B16 + (size_t)(brow + r0g) * ND + kt + c0g * 8);
        cp_async16(st + O_B + swz(r1g, c1g), g_B16 + (size_t)(brow + r1g) * ND + kt + c1g * 8);
    };

    float acc[4][4][4];
#pragma unroll
    for (int a = 0; a < 4; ++a)
#pragma unroll
        for (int b = 0; b < 4; ++b)
#pragma unroll
            for (int c = 0; c < 4; ++c) acc[a][b][c] = 0.f;

    const int g  = lid >> 3;
    const int rr = lid & 7;

    auto compute_stage = [&](int slot) {
        const uint32_t st = sb + (uint32_t)slot * STAGE_BYTES;
#pragma unroll
        for (int ks = 0; ks < 2; ++ks) {
            const int c0 = ks * 2;
            uint32_t ah[4][4], bh[4][2];
#pragma unroll
            for (int tm = 0; tm < 4; ++tm) {
                int r = wm * 64 + tm * 16 + (g & 1) * 8 + rr;
                ldsm4(ah[tm][0], ah[tm][1], ah[tm][2], ah[tm][3],
                      st + O_A + swz(r, c0 + (g >> 1)));
            }
#pragma unroll
            for (int p = 0; p < 2; ++p) {
                int r = wn * 32 + p * 16 + (g >> 1) * 8 + rr;
                uint32_t h0, h1, h2, h3;
                ldsm4(h0, h1, h2, h3, st + O_B + swz(r, c0 + (g & 1)));
                bh[p * 2 + 0][0] = h0; bh[p * 2 + 0][1] = h1;
                bh[p * 2 + 1][0] = h2; bh[p * 2 + 1][1] = h3;
            }
#pragma unroll
            for (int tm = 0; tm < 4; ++tm)
#pragma unroll
                for (int tn = 0; tn < 4; ++tn)
                    mma16816f(acc[tm][tn], ah[tm], bh[tn]);
        }
    };

    // prologue: stages 0,1 (KTc >= 4 always)
    issue(0, kt0);      cp_commit();
    issue(1, kt0 + 32); cp_commit();

    // two K=32 stages per barrier; commits = j+4 -> wait2 completes <= j+1.
    // slot reuse: writes {j+2,j+3} vs laggard reads {j-2,j-1} mod 6 -> safe.
    for (int j = 0; j < KTc; j += 2) {
        if (j + 2 < KTc) issue((j + 2) % STAGES, kt0 + (j + 2) * 32);
        cp_commit();
        if (j + 3 < KTc) issue((j + 3) % STAGES, kt0 + (j + 3) * 32);
        cp_commit();
        cp_wait2();
        __syncthreads();
        compute_stage(j % STAGES);
        compute_stage((j + 1) % STAGES);
    }

    // epilogue: single-chunk tiles store, multi-chunk tiles atomically add
    if (nch == 1) {
#pragma unroll
        for (int tm = 0; tm < 4; ++tm)
#pragma unroll
            for (int tn = 0; tn < 4; ++tn) {
                int row = arow + wm * 64 + tm * 16 + (lid >> 2);
                int col = brow + wn * 32 + tn * 8 + (lid & 3) * 2;
                *(float2*)(C + (size_t)row * ND + col) =
                    make_float2(acc[tm][tn][0], acc[tm][tn][1]);
                *(float2*)(C + (size_t)(row + 8) * ND + col) =
                    make_float2(acc[tm][tn][2], acc[tm][tn][3]);
            }
    } else {
#pragma unroll
        for (int tm = 0; tm < 4; ++tm)
#pragma unroll
            for (int tn = 0; tn < 4; ++tn) {
                int row = arow + wm * 64 + tm * 16 + (lid >> 2);
                int col = brow + wn * 32 + tn * 8 + (lid & 3) * 2;
                float* p0 = C + (size_t)row * ND + col;
                float* p1 = C + (size_t)(row + 8) * ND + col;
                redadd(p0,     acc[tm][tn][0]);
                redadd(p0 + 1, acc[tm][tn][1]);
                redadd(p1,     acc[tm][tn][2]);
                redadd(p1 + 1, acc[tm][tn][3]);
            }
    }
}

// ---------------- launch ----------------------------------------------------
extern "C" void kernel_launch(void* const* d_in, const int* in_sizes, int n_in,
                              void* d_out, int out_size) {
    const float* A = (const float*)d_in[0];
    const float* B = (const float*)d_in[1];
    float* C = (float*)d_out;

    cudaFuncSetAttribute(trimm_gemm, cudaFuncAttributeMaxDynamicSharedMemorySize, GEMM_SMEM);

    convert_A<<<16384, 256>>>(A, C);
    transpose_B<<<dim3(64, 64), dim3(64, 4)>>>(B);
    trimm_gemm<<<UNITS, 256, GEMM_SMEM>>>(C);
}

// round 16
// speedup vs baseline: 2.0680x; 1.0675x over previous
#include <cuda_runtime.h>
#include <cuda_fp16.h>
#include <cstdint>

#define ND 4096
#define NTE (ND * (size_t)ND)

// ---------------- scratch (device globals; no allocation allowed) ----------
__device__ __align__(1024) __half g_A16[NTE];   // fp16(tril(A)), [M,K] K-major
__device__ __align__(1024) __half g_B16[NTE];   // fp16(tril(B)^T), [N,K] K-major

// ---------------- helpers ---------------------------------------------------
static __device__ __forceinline__ uint32_t smem_u32(const void* p) {
    return (uint32_t)__cvta_generic_to_shared(p);
}
static __device__ __forceinline__ void cp_async16(uint32_t dst, const void* src) {
    asm volatile("cp.async.cg.shared.global [%0], [%1], 16;" :: "r"(dst), "l"(src));
}
static __device__ __forceinline__ void cp_commit() {
    asm volatile("cp.async.commit_group;" ::: "memory");
}
static __device__ __forceinline__ void cp_wait2() {
    asm volatile("cp.async.wait_group 2;" ::: "memory");
}
static __device__ __forceinline__ void ldsm4(uint32_t& r0, uint32_t& r1,
                                             uint32_t& r2, uint32_t& r3, uint32_t a) {
    asm volatile("ldmatrix.sync.aligned.m8n8.x4.shared.b16 {%0,%1,%2,%3}, [%4];"
                 : "=r"(r0), "=r"(r1), "=r"(r2), "=r"(r3) : "r"(a));
}
static __device__ __forceinline__ void mma16816f(float* d, const uint32_t* a,
                                                 const uint32_t* b) {
    asm volatile(
        "mma.sync.aligned.m16n8k16.row.col.f32.f16.f16.f32 "
        "{%0,%1,%2,%3}, {%4,%5,%6,%7}, {%8,%9}, {%0,%1,%2,%3};"
        : "+f"(d[0]), "+f"(d[1]), "+f"(d[2]), "+f"(d[3])
        : "r"(a[0]), "r"(a[1]), "r"(a[2]), "r"(a[3]), "r"(b[0]), "r"(b[1]));
}
static __device__ __forceinline__ void redadd(float* p, float v) {
    asm volatile("red.global.add.f32 [%0], %1;" :: "l"(p), "f"(v) : "memory");
}

// swizzled smem byte offset inside one 8KB tile: row r (0..127), 16B chunk c (0..3)
static __device__ __forceinline__ uint32_t swz(int r, int c) {
    return (uint32_t)(r * 64 + ((c ^ ((r >> 1) & 3)) << 4));
}

// ------ pre-pass: zero C + mask + fp16 convert of A (lower blocks only) -----
__global__ void convert_A(const float* __restrict__ A, float* __restrict__ C) {
    size_t idx  = (size_t)blockIdx.x * blockDim.x + threadIdx.x;   // one float4
    size_t base = idx * 4;
    int i = (int)(base >> 12);     // row
    int k = (int)(base & 4095);    // col
    *(float4*)(C + base) = make_float4(0.f, 0.f, 0.f, 0.f);
    if ((k >> 7) > (i >> 7)) return;   // strictly-upper 128-blocks never read
    float4 v = *(const float4*)(A + base);
    float vv[4] = {v.x, v.y, v.z, v.w};
    __half h[4];
#pragma unroll
    for (int e = 0; e < 4; ++e) {
        float x = ((k + e) <= i) ? vv[e] : 0.0f;
        h[e] = __float2half_rn(x);
    }
    *(uint2*)(g_A16 + base) = *(uint2*)h;
}

// ---------------- pre-pass: mask + transpose + fp16 of B (64x64 tiles) ------
__global__ void transpose_B(const float* __restrict__ B) {
    __shared__ float tile[64][65];
    const int bk = blockIdx.y;
    const int bn = blockIdx.x;
    if ((bn >> 1) > (bk >> 1)) return;   // keep only k128-block >= n128-block
    const int tx = threadIdx.x;  // 0..63
    const int ty = threadIdx.y;  // 0..3
    const int k0 = bk * 64, n0 = bn * 64;
#pragma unroll
    for (int r = ty; r < 64; r += 4) {
        int k = k0 + r, n = n0 + tx;
        float v = B[(size_t)k * ND + n];
        tile[r][tx] = (n <= k) ? v : 0.0f;
    }
    __syncthreads();
#pragma unroll
    for (int r = ty; r < 64; r += 4) {
        int n = n0 + r, k = k0 + tx;
        g_B16[(size_t)n * ND + k] = __float2half_rn(tile[tx][r]);
    }
}

// -------- main GEMM: fp16 single product, warp tile 64x32, split-K, occ=2 ---
#define STAGES 6
#define TILE_BYTES 8192                     // one 128x32 fp16 tile
#define O_A 0
#define O_B 8192
#define STAGE_BYTES 16384                   // A + B
#define GEMM_SMEM (STAGES * STAGE_BYTES)    // 98304 -> 2 CTAs/SM
#define CH 32                               // K-stages per chunk (K=1024)
#define UNITS 1000

__global__ __launch_bounds__(256, 2)
void trimm_gemm(float* __restrict__ C) {
    extern __shared__ char smem[];
    const uint32_t sb = smem_u32(smem);
    const int tid = threadIdx.x;
    const int wid = tid >> 5;
    const int lid = tid & 31;
    const int wm = wid & 1;        // 0..1 (M)
    const int wn = wid >> 1;       // 0..3 (N)

    // ---- work-unit map: heaviest diagonals first, chunks within tile -------
    int id = blockIdx.x;
    int d, cum = 0, nch = 1;
    for (d = 31; d >= 0; --d) {
        nch = ((d + 1) * 4 + CH - 1) / CH;
        int cnt = (32 - d) * nch;
        if (id < cum + cnt) break;
        cum += cnt;
    }
    const int rem = id - cum;
    const int bj  = rem / nch;
    const int cch = rem % nch;
    const int bi  = bj + d;

    const int KTtile = (d + 1) * 4;
    const int ks0    = cch * CH;
    const int KTc    = min(CH, KTtile - ks0);  // multiple of 4, >= 4
    const int kt0    = bj * 128 + ks0 * 32;

    const int arow = bi * 128, brow = bj * 128;

    // per-thread cp.async chunk coords: two chunks per 8KB tile
    const int r0g = tid >> 2, c0g = tid & 3;
    const int r1g = (tid + 256) >> 2, c1g = tid & 3;

    auto issue = [&](int s, int kt) {
        uint32_t st = sb + (uint32_t)s * STAGE_BYTES;
        cp_async16(st + O_A + swz(r0g, c0g), g_A16 + (size_t)(arow + r0g) * ND + kt + c0g * 8);
        cp_async16(st + O_A + swz(r1g, c1g), g_A16 + (size_t)(arow + r1g) * ND + kt + c1g * 8);
        cp_async16(st + O_B + swz(r0g, c0g), g_B16 + (size_t)(brow + r0g) * ND + kt + c0g * 8);
        cp_async16(st + O_B + swz(r1g, c1g), g_B16 + (size_t)(brow + r1g) * ND + kt + c1g * 8);
    };

    float acc[4][4][4];
#pragma unroll
    for (int a = 0; a < 4; ++a)
#pragma unroll
        for (int b = 0; b < 4; ++b)
#pragma unroll
            for (int c = 0; c < 4; ++c) acc[a][b][c] = 0.f;

    const int g  = lid >> 3;
    const int rr = lid & 7;

    auto compute_stage = [&](int slot) {
        const uint32_t st = sb + (uint32_t)slot * STAGE_BYTES;
#pragma unroll
        for (int ks = 0; ks < 2; ++ks) {
            const int c0 = ks * 2;
            uint32_t ah[4][4], bh[4][2];
#pragma unroll
            for (int tm = 0; tm < 4; ++tm) {
                int r = wm * 64 + tm * 16 + (g & 1) * 8 + rr;
                ldsm4(ah[tm][0], ah[tm][1], ah[tm][2], ah[tm][3],
                      st + O_A + swz(r, c0 + (g >> 1)));
            }
#pragma unroll
            for (int p = 0; p < 2; ++p) {
                int r = wn * 32 + p * 16 + (g >> 1) * 8 + rr;
                uint32_t h0, h1, h2, h3;
                ldsm4(h0, h1, h2, h3, st + O_B + swz(r, c0 + (g & 1)));
                bh[p * 2 + 0][0] = h0; bh[p * 2 + 0][1] = h1;
                bh[p * 2 + 1][0] = h2; bh[p * 2 + 1][1] = h3;
            }
#pragma unroll
            for (int tm = 0; tm < 4; ++tm)
#pragma unroll
                for (int tn = 0; tn < 4; ++tn)
                    mma16816f(acc[tm][tn], ah[tm], bh[tn]);
        }
    };

    // prologue: stages 0,1 (KTc >= 4 always)
    issue(0, kt0);      cp_commit();
    issue(1, kt0 + 32); cp_commit();

    // two K=32 stages per barrier; commits = j+4 -> wait2 completes <= j+1.
    // slot reuse: writes {j+2,j+3} vs laggard reads {j-2,j-1} mod 6 -> safe.
    for (int j = 0; j < KTc; j += 2) {
        if (j + 2 < KTc) issue((j + 2) % STAGES, kt0 + (j + 2) * 32);
        cp_commit();
        if (j + 3 < KTc) issue((j + 3) % STAGES, kt0 + (j + 3) * 32);
        cp_commit();
        cp_wait2();
        __syncthreads();
        compute_stage(j % STAGES);
        compute_stage((j + 1) % STAGES);
    }

    // epilogue: single-chunk tiles store, multi-chunk tiles atomically add
    if (nch == 1) {
#pragma unroll
        for (int tm = 0; tm < 4; ++tm)
#pragma unroll
            for (int tn = 0; tn < 4; ++tn) {
                int row = arow + wm * 64 + tm * 16 + (lid >> 2);
                int col = brow + wn * 32 + tn * 8 + (lid & 3) * 2;
                *(float2*)(C + (size_t)row * ND + col) =
                    make_float2(acc[tm][tn][0], acc[tm][tn][1]);
                *(float2*)(C + (size_t)(row + 8) * ND + col) =
                    make_float2(acc[tm][tn][2], acc[tm][tn][3]);
            }
    } else {
#pragma unroll
        for (int tm = 0; tm < 4; ++tm)
#pragma unroll
            for (int tn = 0; tn < 4; ++tn) {
                int row = arow + wm * 64 + tm * 16 + (lid >> 2);
                int col = brow + wn * 32 + tn * 8 + (lid & 3) * 2;
                float* p0 = C + (size_t)row * ND + col;
                float* p1 = C + (size_t)(row + 8) * ND + col;
                redadd(p0,     acc[tm][tn][0]);
                redadd(p0 + 1, acc[tm][tn][1]);
                redadd(p1,     acc[tm][tn][2]);
                redadd(p1 + 1, acc[tm][tn][3]);
            }
    }
}

// ---------------- launch ----------------------------------------------------
extern "C" void kernel_launch(void* const* d_in, const int* in_sizes, int n_in,
                              void* d_out, int out_size) {
    const float* A = (const float*)d_in[0];
    const float* B = (const float*)d_in[1];
    float* C = (float*)d_out;

    cudaFuncSetAttribute(trimm_gemm, cudaFuncAttributeMaxDynamicSharedMemorySize, GEMM_SMEM);

    convert_A<<<16384, 256>>>(A, C);
    transpose_B<<<dim3(64, 64), dim3(64, 4)>>>(B);
    trimm_gemm<<<UNITS, 256, GEMM_SMEM>>>(C);
}